// round 17
// baseline (speedup 1.0000x reference)
#include <cuda_runtime.h>
#include <cuda_bf16.h>
#include <cuda_fp16.h>
#include <cstddef>

// Problem constants
#define BB 4
#define HH 128
#define WW 128
#define CC 192
#define NHH 6
#define KD 32
#define MM (BB*HH*WW)          // 65536 tokens
#define SCALING 0.17677669529663687f  // 32^-0.5
#define LOG2E   1.4426950408889634f
#define WSZ (CC*CC)            // 36864

typedef unsigned long long ull;

// Scratch (static device buffers)
static const size_t TENS = (size_t)MM * CC;
__device__ float  g_v[TENS];       // V fp32 (dwconv input)
__device__ float  g_lepe[TENS];
__device__ __half g_x16[TENS];     // x fp16
__device__ __half g_q16[TENS];     // Q * LOG2E fp16
__device__ __half g_k16[TENS];     // K * SCALING fp16
__device__ __half g_v16[TENS];     // V fp16
__device__ __half g_v1h[TENS];     // v1 [b][n][w][h][d] fp16
__device__ __half g_tmp16[TENS];   // attn out + lepe fp16
__device__ __half g_wT[4 * WSZ];   // Wq,Wk,Wv,Wo transposed [n][k] fp16

// ---------------------------------------------------------------------------
// packed f32x2 helpers (dwconv)
// ---------------------------------------------------------------------------
__device__ __forceinline__ ull fma2(ull a, ull b, ull c) {
    ull d;
    asm("fma.rn.f32x2 %0, %1, %2, %3;" : "=l"(d) : "l"(a), "l"(b), "l"(c));
    return d;
}
__device__ __forceinline__ ull pack2(float x, float y) {
    ull r;
    asm("mov.b64 %0, {%1, %2};" : "=l"(r) : "f"(x), "f"(y));
    return r;
}
__device__ __forceinline__ float2 unpack2(ull v) {
    float2 f;
    asm("mov.b64 {%0, %1}, %2;" : "=f"(f.x), "=f"(f.y) : "l"(v));
    return f;
}

// ---------------------------------------------------------------------------
// mma / exp2 helpers
// ---------------------------------------------------------------------------
__device__ __forceinline__ float ex2f(float x) {
    float y;
    asm("ex2.approx.f32 %0, %1;" : "=f"(y) : "f"(x));
    return y;
}
__device__ __forceinline__ unsigned h2u(__half2 h) {
    return *(unsigned*)&h;
}
__device__ __forceinline__ void mma_f16_k16(float* d, const unsigned* a,
                                            unsigned b0, unsigned b1) {
    asm volatile(
        "mma.sync.aligned.m16n8k16.row.col.f32.f16.f16.f32 "
        "{%0,%1,%2,%3}, {%4,%5,%6,%7}, {%8,%9}, {%0,%1,%2,%3};"
        : "+f"(d[0]), "+f"(d[1]), "+f"(d[2]), "+f"(d[3])
        : "r"(a[0]), "r"(a[1]), "r"(a[2]), "r"(a[3]), "r"(b0), "r"(b1));
}
__device__ __forceinline__ void ldmatrix_x4_trans(
    unsigned& r0, unsigned& r1, unsigned& r2, unsigned& r3, unsigned saddr) {
    asm volatile(
        "ldmatrix.sync.aligned.m8n8.x4.trans.shared.b16 {%0,%1,%2,%3}, [%4];"
        : "=r"(r0), "=r"(r1), "=r"(r2), "=r"(r3) : "r"(saddr));
}

// ---------------------------------------------------------------------------
// Prep: x -> fp16
// ---------------------------------------------------------------------------
__global__ __launch_bounds__(256) void cvt_x_kernel(
    const float* __restrict__ x, __half* __restrict__ x16)
{
    size_t i = ((size_t)blockIdx.x * 256 + threadIdx.x) * 4;
    if (i < TENS) {
        float4 v = *(const float4*)&x[i];
        *(unsigned*)&x16[i]     = h2u(__floats2half2_rn(v.x, v.y));
        *(unsigned*)&x16[i + 2] = h2u(__floats2half2_rn(v.z, v.w));
    }
}

// Prep: weights -> transposed fp16 WT[n][k]. grid (6,6,4), block (32,8)
__global__ __launch_bounds__(256) void prep_w_kernel(
    const float* __restrict__ Wq, const float* __restrict__ Wk,
    const float* __restrict__ Wv, const float* __restrict__ Wo,
    __half* __restrict__ wT)
{
    __shared__ float tile[32][33];
    const int z = blockIdx.z;
    const float* W = (z == 0) ? Wq : (z == 1) ? Wk : (z == 2) ? Wv : Wo;
    const int k0 = blockIdx.y * 32, n0 = blockIdx.x * 32;
    const int tx = threadIdx.x, ty = threadIdx.y;
    #pragma unroll
    for (int i = 0; i < 32; i += 8)
        tile[ty + i][tx] = W[(size_t)(k0 + ty + i) * CC + n0 + tx];
    __syncthreads();
    #pragma unroll
    for (int i = 0; i < 32; i += 8)
        wT[(size_t)z * WSZ + (size_t)(n0 + ty + i) * CC + k0 + tx] =
            __float2half_rn(tile[tx][ty + i]);
}

// ---------------------------------------------------------------------------
// fp16 GEMM core (row0/col0 passed in; grid order chosen by caller so that
// all blocks sharing an A row-tile run in the same wave -> A is L2-resident
// and read from DRAM once).
// ---------------------------------------------------------------------------
__device__ __forceinline__ void gemm_f16_core(
    const __half* __restrict__ A, const __half* __restrict__ WT,
    const float* __restrict__ bias, float* __restrict__ outf,
    __half* __restrict__ outh, float scale, int row0, int col0)
{
    __shared__ unsigned As[128 * 24];
    __shared__ unsigned Bs[64 * 24];

    const int t    = threadIdx.x;
    const int warp = t >> 5;
    const int lane = t & 31;
    const int g    = lane >> 2;
    const int t4   = lane & 3;
    const int wm   = (warp >> 1) * 32;
    const int wn   = (warp & 1) * 32;

    const int a_r  = t >> 2;
    const int ch   = t & 3;
    const int sb   = ((ch & 2) << 2) + (ch & 1);

    float acc[2][4][4];
    #pragma unroll
    for (int mt = 0; mt < 2; mt++)
        #pragma unroll
        for (int nt = 0; nt < 4; nt++)
            #pragma unroll
            for (int i = 0; i < 4; i++) acc[mt][nt][i] = 0.f;

    uint4 aReg[2], bReg;
    #pragma unroll
    for (int i = 0; i < 2; i++)
        aReg[i] = *(const uint4*)&A[(size_t)(row0 + a_r + i * 64) * CC + ch * 8];
    bReg = *(const uint4*)&WT[(size_t)(col0 + a_r) * CC + ch * 8];

    for (int kbi = 0; kbi < 6; kbi++) {
        #pragma unroll
        for (int i = 0; i < 2; i++) {
            unsigned* row = As + (a_r + i * 64) * 24 + sb;
            row[0] = aReg[i].x; row[2] = aReg[i].y;
            row[4] = aReg[i].z; row[6] = aReg[i].w;
        }
        {
            unsigned* row = Bs + a_r * 24 + sb;
            row[0] = bReg.x; row[2] = bReg.y;
            row[4] = bReg.z; row[6] = bReg.w;
        }
        __syncthreads();

        if (kbi < 5) {
            int kn = (kbi + 1) * 32;
            #pragma unroll
            for (int i = 0; i < 2; i++)
                aReg[i] = *(const uint4*)&A[(size_t)(row0 + a_r + i * 64) * CC + kn + ch * 8];
            bReg = *(const uint4*)&WT[(size_t)(col0 + a_r) * CC + kn + ch * 8];
        }

        #pragma unroll
        for (int ks = 0; ks < 2; ks++) {
            int b2 = ks * 8 + 2 * t4;
            unsigned a[2][4];
            #pragma unroll
            for (int mt = 0; mt < 2; mt++) {
                uint2 lo = *(const uint2*)&As[(wm + mt * 16 + g    ) * 24 + b2];
                uint2 hi = *(const uint2*)&As[(wm + mt * 16 + 8 + g) * 24 + b2];
                a[mt][0] = lo.x; a[mt][1] = hi.x;
                a[mt][2] = lo.y; a[mt][3] = hi.y;
            }
            #pragma unroll
            for (int nt = 0; nt < 4; nt++) {
                uint2 bf = *(const uint2*)&Bs[(wn + nt * 8 + g) * 24 + b2];
                mma_f16_k16(acc[0][nt], a[0], bf.x, bf.y);
                mma_f16_k16(acc[1][nt], a[1], bf.x, bf.y);
            }
        }
        __syncthreads();
    }

    #pragma unroll
    for (int mt = 0; mt < 2; mt++) {
        int r0 = row0 + wm + mt * 16 + g;
        #pragma unroll
        for (int nt = 0; nt < 4; nt++) {
            int c = col0 + wn + nt * 8 + t4 * 2;
            float bx = bias[c], by = bias[c + 1];
            float o00 = (acc[mt][nt][0] + bx) * scale;
            float o01 = (acc[mt][nt][1] + by) * scale;
            float o10 = (acc[mt][nt][2] + bx) * scale;
            float o11 = (acc[mt][nt][3] + by) * scale;
            if (outf) {
                *(float2*)&outf[(size_t)r0 * CC + c]       = make_float2(o00, o01);
                *(float2*)&outf[(size_t)(r0 + 8) * CC + c] = make_float2(o10, o11);
            }
            if (outh) {
                *(unsigned*)&outh[(size_t)r0 * CC + c]       = h2u(__floats2half2_rn(o00, o01));
                *(unsigned*)&outh[(size_t)(r0 + 8) * CC + c] = h2u(__floats2half2_rn(o10, o11));
            }
        }
    }
}

// Fused QKV: grid (9, 512). blockIdx.x = col*3 + z (the 9 siblings of one
// A row-tile are wave-adjacent -> A read from DRAM once, then L2 hits).
__global__ __launch_bounds__(256, 2) void gemm_qkv_kernel(
    const __half* __restrict__ x16, const __half* __restrict__ wT,
    const float* __restrict__ bq, const float* __restrict__ bk,
    const float* __restrict__ bv,
    __half* __restrict__ q16, __half* __restrict__ k16,
    float* __restrict__ v32, __half* __restrict__ v16)
{
    const int z    = blockIdx.x % 3;
    const int col0 = (blockIdx.x / 3) * 64;
    const int row0 = blockIdx.y * 128;
    const __half* WT  = wT + (size_t)z * WSZ;
    const float* bias = (z == 0) ? bq : (z == 1) ? bk : bv;
    float scale       = (z == 0) ? LOG2E : (z == 1) ? SCALING : 1.0f;
    float* outf       = (z == 2) ? v32 : nullptr;
    __half* outh      = (z == 0) ? q16 : (z == 1) ? k16 : v16;
    gemm_f16_core(x16, WT, bias, outf, outh, scale, row0, col0);
}

// Out GEMM: grid (3, 512), col fastest for the same L2-reuse reason.
__global__ __launch_bounds__(256, 2) void gemm_out_kernel(
    const __half* __restrict__ tmp16, const __half* __restrict__ wT,
    const float* __restrict__ bias, float* __restrict__ out)
{
    gemm_f16_core(tmp16, wT + 3 * (size_t)WSZ, bias, out, nullptr, 1.0f,
                  blockIdx.y * 128, blockIdx.x * 64);
}

// ---------------------------------------------------------------------------
// Depthwise 5x5 conv (unchanged)
// ---------------------------------------------------------------------------
__global__ __launch_bounds__(192) void dwconv_kernel(
    const float* __restrict__ v, const float* __restrict__ kw,
    const float* __restrict__ kb, float* __restrict__ lepe)
{
    __shared__ ull skw[25][48][2];
    const int tid = threadIdx.y * 48 + threadIdx.x;
    for (int i = tid; i < 25 * 48; i += 192) {
        int tap = i / 48, cg = i % 48;
        float4 kk = *(const float4*)&kw[tap * CC + cg * 4];
        skw[tap][cg][0] = pack2(kk.x, kk.y);
        skw[tap][cg][1] = pack2(kk.z, kk.w);
    }
    __syncthreads();

    const int c4 = threadIdx.x;
    const int c  = c4 * 4;
    const int w0 = blockIdx.x * 16 + threadIdx.y * 4;
    const int h0 = blockIdx.y * 2;
    const int b  = blockIdx.z;

    float4 bz = *(const float4*)&kb[c];
    ull ax[2][4], ay[2][4];
    #pragma unroll
    for (int r = 0; r < 2; r++)
        #pragma unroll
        for (int o = 0; o < 4; o++) {
            ax[r][o] = pack2(bz.x, bz.y);
            ay[r][o] = pack2(bz.z, bz.w);
        }

    #pragma unroll
    for (int yy = 0; yy < 6; yy++) {
        int y = h0 - 2 + yy;
        if ((unsigned)y >= HH) continue;
        const float* vrow = v + ((size_t)(b * HH + y) * WW) * CC + c;
        ull txp[8], typ[8];
        #pragma unroll
        for (int j = 0; j < 8; j++) {
            int x = w0 - 2 + j;
            float4 vv = ((unsigned)x < WW) ? *(const float4*)(vrow + (size_t)x * CC)
                                           : make_float4(0.f, 0.f, 0.f, 0.f);
            txp[j] = pack2(vv.x, vv.y);
            typ[j] = pack2(vv.z, vv.w);
        }
        if (yy < 5) {
            #pragma unroll
            for (int dx = 0; dx < 5; dx++) {
                ull k01 = skw[yy * 5 + dx][c4][0];
                ull k23 = skw[yy * 5 + dx][c4][1];
                #pragma unroll
                for (int o = 0; o < 4; o++) {
                    ax[0][o] = fma2(txp[o + dx], k01, ax[0][o]);
                    ay[0][o] = fma2(typ[o + dx], k23, ay[0][o]);
                }
            }
        }
        if (yy >= 1) {
            #pragma unroll
            for (int dx = 0; dx < 5; dx++) {
                ull k01 = skw[(yy - 1) * 5 + dx][c4][0];
                ull k23 = skw[(yy - 1) * 5 + dx][c4][1];
                #pragma unroll
                for (int o = 0; o < 4; o++) {
                    ax[1][o] = fma2(txp[o + dx], k01, ax[1][o]);
                    ay[1][o] = fma2(typ[o + dx], k23, ay[1][o]);
                }
            }
        }
    }
    #pragma unroll
    for (int r = 0; r < 2; r++)
        #pragma unroll
        for (int o = 0; o < 4; o++) {
            float2 fx = unpack2(ax[r][o]), fy = unpack2(ay[r][o]);
            *(float4*)&lepe[((size_t)(b * HH + h0 + r) * WW + w0 + o) * CC + c] =
                make_float4(fx.x, fx.y, fy.x, fy.y);
        }
}

// ===========================================================================
// fp16 tensor-core attention (unchanged from R16: jt-paired PV k16,
// ones-column row sums, raw masks via fmaf)
// ===========================================================================
#define QPITCH 20
#define KPITCH 24
#define VPITCH 20
#define SM_Q 0
#define SM_K (128*QPITCH)
#define SM_V (128*QPITCH + 128*KPITCH)
#define SMEM_ATTN_WORDS (128*(QPITCH+KPITCH+VPITCH))   // 32KB
#define ONES_H2 0x3C003C00u

__device__ __forceinline__ void attn_load_tiles(
    unsigned* Qs, unsigned* Ks, unsigned* Vs,
    const __half* qb, const __half* kb, const __half* vb,
    size_t qk_stride, size_t v_stride, int t)
{
    #pragma unroll
    for (int i = 0; i < 2; i++) {
        int idx = t + i * 256;
        int r = idx >> 2, ch = idx & 3;
        uint4 x = *(const uint4*)(qb + (size_t)r * qk_stride + ch * 8);
        unsigned* dst = Qs + r * QPITCH + ch * 4;
        dst[0] = x.x; dst[1] = x.y; dst[2] = x.z; dst[3] = x.w;
    }
    #pragma unroll
    for (int i = 0; i < 2; i++) {
        int idx = t + i * 256;
        int r = idx >> 2, ch = idx & 3;
        uint4 x = *(const uint4*)(kb + (size_t)r * qk_stride + ch * 8);
        unsigned* row = Ks + r * KPITCH;
        #pragma unroll
        for (int j = 0; j < 4; j++) {
            int p  = ch * 4 + j;
            int pq = p & 7;
            int slot = (p & 8) + 2 * (pq & 3) + (pq >> 2);
            unsigned val = (j == 0) ? x.x : (j == 1) ? x.y : (j == 2) ? x.z : x.w;
            row[slot] = val;
        }
    }
    #pragma unroll
    for (int i = 0; i < 2; i++) {
        int idx = t + i * 256;
        int r = idx >> 2, ch = idx & 3;
        uint4 x = *(const uint4*)(vb + (size_t)r * v_stride + ch * 8);
        unsigned* dst = Vs + r * VPITCH + ch * 4;
        dst[0] = x.x; dst[1] = x.y; dst[2] = x.z; dst[3] = x.w;
    }
}

struct AttnOut { float acc[4][4]; float inv0, inv1; };

__device__ __forceinline__ void attn_core(
    const unsigned* Qs, const unsigned* Ks, const unsigned* Vs,
    const float* mrow0, const float* mrow1,
    int w0, int g, int t4, int lane, AttnOut& out)
{
    unsigned qa[2][4];
    #pragma unroll
    for (int ks = 0; ks < 2; ks++) {
        int b2 = ks * 8;
        qa[ks][0] = Qs[(w0 + g    ) * QPITCH + b2 + t4];
        qa[ks][1] = Qs[(w0 + 8 + g) * QPITCH + b2 + t4];
        qa[ks][2] = Qs[(w0 + g    ) * QPITCH + b2 + t4 + 4];
        qa[ks][3] = Qs[(w0 + 8 + g) * QPITCH + b2 + t4 + 4];
    }

    unsigned vsbase = (unsigned)__cvta_generic_to_shared(Vs);
    unsigned vlane_off = ((lane & 7) * VPITCH + (lane >> 3) * 4) * 4;

    float accO[4][4];
    #pragma unroll
    for (int nt = 0; nt < 4; nt++)
        #pragma unroll
        for (int i = 0; i < 4; i++) accO[nt][i] = 0.f;
    float accR[4] = {0.f, 0.f, 0.f, 0.f};

    for (int jt2 = 0; jt2 < 8; jt2++) {
        unsigned a4[4];
        unsigned vbp[2][4];
        #pragma unroll
        for (int hf = 0; hf < 2; hf++) {
            int jt = jt2 * 2 + hf;
            const unsigned* kr = Ks + (jt * 8 + g) * KPITCH + 2 * t4;
            uint2 kb0 = *(const uint2*)(kr);
            uint2 kb1 = *(const uint2*)(kr + 8);
            float sc[4] = {0.f, 0.f, 0.f, 0.f};
            mma_f16_k16(sc, qa[0], kb0.x, kb0.y);
            mma_f16_k16(sc, qa[1], kb1.x, kb1.y);

            int uc = jt * 8 + 2 * t4;
            float2 m01 = *(const float2*)&mrow0[uc];
            float2 m23 = *(const float2*)&mrow1[uc];
            float p0 = ex2f(fmaf(m01.x, LOG2E, sc[0]));
            float p1 = ex2f(fmaf(m01.y, LOG2E, sc[1]));
            float p2 = ex2f(fmaf(m23.x, LOG2E, sc[2]));
            float p3 = ex2f(fmaf(m23.y, LOG2E, sc[3]));
            a4[hf]     = h2u(__floats2half2_rn(p0, p1));
            a4[hf + 2] = h2u(__floats2half2_rn(p2, p3));
            ldmatrix_x4_trans(vbp[hf][0], vbp[hf][1], vbp[hf][2], vbp[hf][3],
                              vsbase + (jt * 8 * VPITCH) * 4 + vlane_off);
        }
        unsigned af[4] = {a4[0], a4[2], a4[1], a4[3]};
        mma_f16_k16(accO[0], af, vbp[0][0], vbp[1][0]);
        mma_f16_k16(accO[1], af, vbp[0][1], vbp[1][1]);
        mma_f16_k16(accO[2], af, vbp[0][2], vbp[1][2]);
        mma_f16_k16(accO[3], af, vbp[0][3], vbp[1][3]);
        mma_f16_k16(accR, af, ONES_H2, ONES_H2);
    }

    out.inv0 = 1.f / accR[0];
    out.inv1 = 1.f / accR[2];
    #pragma unroll
    for (int nt = 0; nt < 4; nt++)
        #pragma unroll
        for (int i = 0; i < 4; i++) out.acc[nt][i] = accO[nt][i];
}

// Row (width-axis) attention: block (h, n, b). Writes v1h fp16.
__global__ __launch_bounds__(256, 4) void row_attn_mma_kernel(
    const __half* __restrict__ q16, const __half* __restrict__ k16,
    const __half* __restrict__ v16, const float* __restrict__ mask,
    __half* __restrict__ v1h)
{
    extern __shared__ unsigned sm[];
    unsigned* Qs = sm + SM_Q;
    unsigned* Ks = sm + SM_K;
    unsigned* Vs = sm + SM_V;

    const int h = blockIdx.x, n = blockIdx.y, b = blockIdx.z;
    const int t    = threadIdx.x;
    const int warp = t >> 5;
    const int lane = t & 31;
    const int g    = lane >> 2;
    const int t4   = lane & 3;

    const size_t base = ((size_t)(b * HH + h) * WW) * CC + n * KD;
    attn_load_tiles(Qs, Ks, Vs, q16 + base, k16 + base, v16 + base, CC, CC, t);
    __syncthreads();

    const int w0 = warp * 16;
    const float* mrow0 = mask + ((size_t)n * WW + (w0 + g    )) * WW;
    const float* mrow1 = mask + ((size_t)n * WW + (w0 + 8 + g)) * WW;

    AttnOut o;
    attn_core(Qs, Ks, Vs, mrow0, mrow1, w0, g, t4, lane, o);

    const size_t vb = ((((size_t)b * NHH + n) * WW) * HH + h) * KD;
    #pragma unroll
    for (int nt = 0; nt < 4; nt++) {
        int d = nt * 8 + 2 * t4;
        *(unsigned*)&v1h[vb + (size_t)(w0 + g) * (HH * KD) + d] =
            h2u(__floats2half2_rn(o.acc[nt][0] * o.inv0, o.acc[nt][1] * o.inv0));
        *(unsigned*)&v1h[vb + (size_t)(w0 + 8 + g) * (HH * KD) + d] =
            h2u(__floats2half2_rn(o.acc[nt][2] * o.inv1, o.acc[nt][3] * o.inv1));
    }
}

// Column (height-axis) attention + lepe: block (w, n, b). Writes tmp16 fp16.
__global__ __launch_bounds__(256, 4) void col_attn_mma_kernel(
    const __half* __restrict__ q16, const __half* __restrict__ k16,
    const __half* __restrict__ v1h, const float* __restrict__ mask,
    const float* __restrict__ lepe, __half* __restrict__ outp)
{
    extern __shared__ unsigned sm[];
    unsigned* Qs = sm + SM_Q;
    unsigned* Ks = sm + SM_K;
    unsigned* Vs = sm + SM_V;

    const int w = blockIdx.x, n = blockIdx.y, b = blockIdx.z;
    const int t    = threadIdx.x;
    const int warp = t >> 5;
    const int lane = t & 31;
    const int g    = lane >> 2;
    const int t4   = lane & 3;

    const size_t qk_base = ((size_t)b * HH * WW + w) * CC + n * KD;
    const size_t jstride = (size_t)WW * CC;
    const size_t v1base  = (((size_t)b * NHH + n) * WW + w) * (size_t)(HH * KD);

    attn_load_tiles(Qs, Ks, Vs, q16 + qk_base, k16 + qk_base, v1h + v1base,
                    jstride, KD, t);
    __syncthreads();

    const int w0 = warp * 16;
    const float* mrow0 = mask + ((size_t)n * HH + (w0 + g    )) * HH;
    const float* mrow1 = mask + ((size_t)n * HH + (w0 + 8 + g)) * HH;

    AttnOut o;
    attn_core(Qs, Ks, Vs, mrow0, mrow1, w0, g, t4, lane, o);

    #pragma unroll
    for (int nt = 0; nt < 4; nt++) {
        int d = nt * 8 + 2 * t4;
        size_t o0 = ((size_t)(b * HH + (w0 + g    )) * WW + w) * CC + n * KD + d;
        size_t o1 = ((size_t)(b * HH + (w0 + 8 + g)) * WW + w) * CC + n * KD + d;
        float2 l0 = *(const float2*)&lepe[o0];
        float2 l1 = *(const float2*)&lepe[o1];
        *(unsigned*)&outp[o0] = h2u(__floats2half2_rn(
            o.acc[nt][0] * o.inv0 + l0.x, o.acc[nt][1] * o.inv0 + l0.y));
        *(unsigned*)&outp[o1] = h2u(__floats2half2_rn(
            o.acc[nt][2] * o.inv1 + l1.x, o.acc[nt][3] * o.inv1 + l1.y));
    }
}

// ---------------------------------------------------------------------------
extern "C" void kernel_launch(void* const* d_in, const int* in_sizes, int n_in,
                              void* d_out, int out_size)
{
    const float* x      = (const float*)d_in[0];
    const float* mask_h = (const float*)d_in[1];
    const float* mask_w = (const float*)d_in[2];
    const float* Wq     = (const float*)d_in[3];
    const float* bq     = (const float*)d_in[4];
    const float* Wk     = (const float*)d_in[5];
    const float* bk     = (const float*)d_in[6];
    const float* Wv     = (const float*)d_in[7];
    const float* bv     = (const float*)d_in[8];
    const float* lepe_w = (const float*)d_in[9];
    const float* lepe_b = (const float*)d_in[10];
    const float* Wo     = (const float*)d_in[11];
    const float* bo     = (const float*)d_in[12];
    float* out = (float*)d_out;

    float *pv, *plepe;
    __half *px16, *pq16, *pk16, *pv16, *pv1h, *ptmp16, *pwT;
    cudaGetSymbolAddress((void**)&pv,     g_v);
    cudaGetSymbolAddress((void**)&plepe,  g_lepe);
    cudaGetSymbolAddress((void**)&px16,   g_x16);
    cudaGetSymbolAddress((void**)&pq16,   g_q16);
    cudaGetSymbolAddress((void**)&pk16,   g_k16);
    cudaGetSymbolAddress((void**)&pv16,   g_v16);
    cudaGetSymbolAddress((void**)&pv1h,   g_v1h);
    cudaGetSymbolAddress((void**)&ptmp16, g_tmp16);
    cudaGetSymbolAddress((void**)&pwT,    g_wT);

    const int SMEM_ATTN = SMEM_ATTN_WORDS * 4;   // 32,768 B
    cudaFuncSetAttribute(row_attn_mma_kernel,
                         cudaFuncAttributeMaxDynamicSharedMemorySize, SMEM_ATTN);
    cudaFuncSetAttribute(col_attn_mma_kernel,
                         cudaFuncAttributeMaxDynamicSharedMemorySize, SMEM_ATTN);

    // Prep
    cvt_x_kernel<<<(int)((TENS / 4 + 255) / 256), 256>>>(x, px16);
    prep_w_kernel<<<dim3(6, 6, 4), dim3(32, 8)>>>(Wq, Wk, Wv, Wo, pwT);

    // Grid ordered (col*3+z, row): siblings of an A row-tile are wave-adjacent.
    gemm_qkv_kernel<<<dim3(9, MM / 128), 256>>>(px16, pwT, bq, bk, bv,
                                                pq16, pk16, pv, pv16);

    dwconv_kernel<<<dim3(WW / 16, HH / 2, BB), dim3(48, 4)>>>(pv, lepe_w, lepe_b, plepe);

    row_attn_mma_kernel<<<dim3(HH, NHH, BB), 256, SMEM_ATTN>>>(pq16, pk16, pv16, mask_w, pv1h);
    col_attn_mma_kernel<<<dim3(WW, NHH, BB), 256, SMEM_ATTN>>>(pq16, pk16, pv1h, mask_h, plepe, ptmp16);

    gemm_out_kernel<<<dim3(3, MM / 128), 256>>>(ptmp16, pwT, bo, out);
}